// round 1
// baseline (speedup 1.0000x reference)
#include <cuda_runtime.h>

// AdEx neuron scan, T=2048, N=32768.
// Key facts (from reference constants):
//   TAU_M = C/g_L = 20, DT/TAU_M = 0.005
//   A = 0, B = 0  =>  w(t) == 0 exactly for all t and all inputs (w0 = 0,
//                     dw = -w/tau_w, spike adds B=0). w is dropped.
// Common path (exact to below-f32-significance when V <= -20):
//   V' = 0.995*V + 0.005*(I - 70)
// Rare path (warp-uniform branch, taken only if any lane could be affected):
//   full update including 2*exp((V-0.6)/2) and spike/reset handling.
// This keeps MUFU.EX2 (the would-be bottleneck: ~480us chip-wide if executed
// every step) off the hot path, leaving a pure stream: 256MB read + 256MB write.

#define AX_N 32768
#define AX_UNROLL 32

__global__ void __launch_bounds__(256, 1)
adex_kernel(const float* __restrict__ I, float* __restrict__ S, int T) {
    const int n = blockIdx.x * blockDim.x + threadIdx.x;
    if (n >= AX_N) return;

    const float* ip = I + n;
    float* op = S + n;

    float V = -70.0f;   // E_L

    int t = 0;
    for (; t + AX_UNROLL <= T; t += AX_UNROLL) {
        // Front-batched independent loads: 32 LDGs in flight per thread
        // (MLP for DRAM latency hiding at ~8 warps/SM).
        float iv[AX_UNROLL];
        #pragma unroll
        for (int k = 0; k < AX_UNROLL; ++k)
            iv[k] = __ldcs(ip + (size_t)(t + k) * AX_N);

        #pragma unroll
        for (int k = 0; k < AX_UNROLL; ++k) {
            const float Vold = V;
            // cheap linear update: 2 FFMA (exp term < f32 significance here)
            float Vn = fmaf(0.995f, Vold, fmaf(0.005f, iv[k], -0.35f));
            float s = 0.0f;
            // Rare-path guard. Warp-vote makes the branch uniform so ptxas
            // emits a real BRA instead of predicating MUFU onto the hot path.
            const bool rare = (Vold > -20.0f) || (Vn >= 30.0f);
            if (__any_sync(0xFFFFFFFFu, rare)) {
                // Exact AdEx update (matches reference; w == 0 dropped).
                const float e = 2.0f * __expf((Vold - 0.6f) * 0.5f);
                Vn = Vold + 0.005f * ((-70.0f - Vold) + e + iv[k]);
                if (Vn >= 30.0f) { s = 1.0f; Vn = -65.0f; }
            }
            V = Vn;
            __stcs(op + (size_t)(t + k) * AX_N, s);
        }
    }

    // Tail (not hit for T=2048, kept for generality): always-exact path.
    for (; t < T; ++t) {
        const float iv = __ldcs(ip + (size_t)t * AX_N);
        const float Vold = V;
        const float e = 2.0f * __expf((Vold - 0.6f) * 0.5f);
        float Vn = Vold + 0.005f * ((-70.0f - Vold) + e + iv);
        float s = 0.0f;
        if (Vn >= 30.0f) { s = 1.0f; Vn = -65.0f; }
        V = Vn;
        __stcs(op + (size_t)t * AX_N, s);
    }
}

extern "C" void kernel_launch(void* const* d_in, const int* in_sizes, int n_in,
                              void* d_out, int out_size) {
    const float* I = (const float*)d_in[0];
    float* S = (float*)d_out;
    const int T = in_sizes[0] / AX_N;   // 2048
    const int block = 256;
    const int grid = (AX_N + block - 1) / block;  // 128 blocks
    adex_kernel<<<grid, block>>>(I, S, T);
}

// round 2
// speedup vs baseline: 1.2582x; 1.2582x over previous
#include <cuda_runtime.h>

// AdEx neuron scan, T=2048, N=32768. spikes[t,n] = f32 0/1.
// w == 0 identically (A=0, B=0, w0=0) -> dropped.
// Fast path (valid while trajectory stays <= -20 mV, where the exponential
// term 2*exp((V-0.6)/2) < 7e-5 and cannot influence spiking; on this input
// V ~ -70 +/- 0.05):   V' = 0.995*V + 0.005*(I - 70),   spike = 0.
// Rare path: exact per-batch redo (exp + spike/reset) from saved batch-start V.
//
// R2 change vs R1: double-buffered software pipeline (loads of batch i+1 in
// flight during compute/store of batch i) + one warp-vote per 32-step batch
// instead of per step. Targets the exposed DRAM latency (R1: 43.7% DRAM).

#define AX_N 32768
#define U 32

__device__ __forceinline__ void load_batch(const float* __restrict__ ip,
                                           int tbase, float (&buf)[U]) {
    #pragma unroll
    for (int k = 0; k < U; ++k)
        buf[k] = __ldcs(ip + (size_t)(tbase + k) * AX_N);
}

__device__ __forceinline__ void compute_batch(float* __restrict__ op, int tbase,
                                              const float (&buf)[U], float& V) {
    const float Vs = V;
    float m = V;
    float v = V;
    #pragma unroll
    for (int k = 0; k < U; ++k) {
        v = fmaf(0.995f, v, fmaf(0.005f, buf[k], -0.35f));
        m = fmaxf(m, v);
        __stcs(op + (size_t)(tbase + k) * AX_N, 0.0f);
    }
    if (__any_sync(0xFFFFFFFFu, m > -20.0f)) {
        // Exact AdEx redo for this batch (rare; correctness fallback).
        v = Vs;
        #pragma unroll 1
        for (int k = 0; k < U; ++k) {
            const float e = 2.0f * expf((v - 0.6f) * 0.5f);
            float Vn = v + 0.005f * ((-70.0f - v) + e + buf[k]);
            float s = 0.0f;
            if (Vn >= 30.0f) { s = 1.0f; Vn = -65.0f; }
            v = Vn;
            __stcs(op + (size_t)(tbase + k) * AX_N, s);
        }
    }
    V = v;
}

__global__ void __launch_bounds__(256, 1)
adex_kernel(const float* __restrict__ I, float* __restrict__ S, int T) {
    const int n = blockIdx.x * blockDim.x + threadIdx.x;
    if (n >= AX_N) return;

    const float* ip = I + n;
    float* op = S + n;

    float V = -70.0f;   // E_L
    float bufA[U], bufB[U];

    const int nb = T / U;          // 64 full batches for T=2048
    int t = 0;

    if (nb > 0) {
        load_batch(ip, 0, bufA);
        // Pipelined pairs: prefetch the other buffer, then compute current.
        int b = 0;
        for (; b + 2 <= nb; b += 2) {
            load_batch(ip, (b + 1) * U, bufB);       // in flight during...
            compute_batch(op, b * U, bufA, V);       // ...this compute
            if (b + 2 < nb) load_batch(ip, (b + 2) * U, bufA);
            compute_batch(op, (b + 1) * U, bufB, V);
        }
        if (b < nb) {                                // odd nb tail batch
            compute_batch(op, b * U, bufA, V);
            b++;
        }
        t = nb * U;
    }

    // Scalar tail (T % U != 0): always-exact path.
    for (; t < T; ++t) {
        const float iv = __ldcs(ip + (size_t)t * AX_N);
        const float e = 2.0f * expf((V - 0.6f) * 0.5f);
        float Vn = V + 0.005f * ((-70.0f - V) + e + iv);
        float s = 0.0f;
        if (Vn >= 30.0f) { s = 1.0f; Vn = -65.0f; }
        V = Vn;
        __stcs(op + (size_t)t * AX_N, s);
    }
}

extern "C" void kernel_launch(void* const* d_in, const int* in_sizes, int n_in,
                              void* d_out, int out_size) {
    const float* I = (const float*)d_in[0];
    float* S = (float*)d_out;
    const int T = in_sizes[0] / AX_N;   // 2048
    adex_kernel<<<AX_N / 256, 256>>>(I, S, T);
}

// round 3
// speedup vs baseline: 1.3108x; 1.0418x over previous
#include <cuda_runtime.h>

// AdEx neuron scan, T=2048, N=32768. spikes[t,n] in f32 {0,1}.
// w == 0 identically (A=0, B=0, w0=0) -> dropped.
// Fast path (valid while V <= -20 mV, where 2*exp((V-0.6)/2) < 7e-5 cannot
// affect spiking):  V' = 0.995*V + 0.005*(I - 70), spike = 0.
// Rare path: exact per-batch redo (exp + spike/reset) from saved batch-start V.
//
// R3 change vs R2: stores decoupled from the scan. Fast path stores are
// always 0.0 and independent of the scan, so zeros are written in bulk with
// coalesced STG.128 (4x fewer store instrs, ~3x fewer LSU cycles), and the
// scan itself issues no stores. A per-batch __syncthreads orders the rare
// fallback's overwrites behind that batch's zero-fill (block owns its neuron
// columns, so block-local ordering is sufficient). Grid 256x128 covers all
// 148 SMs (R2 used 128 blocks -> 20 SMs idle).

#define AX_N 32768
#define U 32
#define BLK 128

__device__ __forceinline__ void load_batch(const float* __restrict__ ip,
                                           int tbase, float (&buf)[U]) {
    #pragma unroll
    for (int k = 0; k < U; ++k)
        buf[k] = __ldcs(ip + (size_t)(tbase + k) * AX_N);
}

// Bulk-zero rows [tbase, tbase+U) x this block's 128 neuron columns.
// 32 rows x 128 floats = 1024 float4 = 8 per thread. Row = 32 float4 ->
// one warp-wide STG.128 per row, fully coalesced.
__device__ __forceinline__ void zero_batch(float* __restrict__ S, int tbase,
                                           int n0, int tid) {
    #pragma unroll
    for (int i = 0; i < 8; ++i) {
        const int idx = tid + i * BLK;
        const int row = idx >> 5;          // 0..31
        const int col4 = idx & 31;         // 0..31
        float4* p = (float4*)(S + (size_t)(tbase + row) * AX_N + n0) + col4;
        __stcs(p, make_float4(0.f, 0.f, 0.f, 0.f));
    }
}

// Scan one batch. Fast path: no stores. Rare path: exact redo with stores
// (overwrites the zeros written by zero_batch for these rows).
__device__ __forceinline__ void compute_batch(float* __restrict__ op, int tbase,
                                              const float (&buf)[U], float& V) {
    const float Vs = V;
    float v = V;
    float m = V;
    #pragma unroll
    for (int k = 0; k < U; ++k) {
        v = fmaf(0.995f, v, fmaf(0.005f, buf[k], -0.35f));
        m = fmaxf(m, v);
    }
    if (__any_sync(0xFFFFFFFFu, m > -20.0f)) {
        // Exact AdEx redo for this batch (rare; correctness fallback).
        v = Vs;
        #pragma unroll 1
        for (int k = 0; k < U; ++k) {
            const float e = 2.0f * expf((v - 0.6f) * 0.5f);
            float Vn = v + 0.005f * ((-70.0f - v) + e + buf[k]);
            float s = 0.0f;
            if (Vn >= 30.0f) { s = 1.0f; Vn = -65.0f; }
            v = Vn;
            __stcs(op + (size_t)(tbase + k) * AX_N, s);
        }
    }
    V = v;
}

__global__ void __launch_bounds__(BLK)
adex_kernel(const float* __restrict__ I, float* __restrict__ S, int T) {
    const int tid = threadIdx.x;
    const int n0 = blockIdx.x * BLK;
    const int n = n0 + tid;
    if (n >= AX_N) return;

    const float* ip = I + n;
    float* op = S + n;

    float V = -70.0f;   // E_L
    float bufA[U], bufB[U];

    const int nb = T / U;          // 64 for T=2048
    int t = 0;

    if (nb > 0) {
        load_batch(ip, 0, bufA);
        int b = 0;
        for (; b + 2 <= nb; b += 2) {
            load_batch(ip, (b + 1) * U, bufB);   // prefetch next
            zero_batch(S, b * U, n0, tid);       // bulk zeros for batch b
            __syncthreads();                     // zeros(b) before fallback(b)
            compute_batch(op, b * U, bufA, V);

            if (b + 2 < nb) load_batch(ip, (b + 2) * U, bufA);
            zero_batch(S, (b + 1) * U, n0, tid);
            __syncthreads();
            compute_batch(op, (b + 1) * U, bufB, V);
        }
        if (b < nb) {                            // odd nb
            zero_batch(S, b * U, n0, tid);
            __syncthreads();
            compute_batch(op, b * U, bufA, V);
            b++;
        }
        t = nb * U;
    }

    // Scalar tail (T % U != 0): always-exact path with direct stores.
    for (; t < T; ++t) {
        const float iv = __ldcs(ip + (size_t)t * AX_N);
        const float e = 2.0f * expf((V - 0.6f) * 0.5f);
        float Vn = V + 0.005f * ((-70.0f - V) + e + iv);
        float s = 0.0f;
        if (Vn >= 30.0f) { s = 1.0f; Vn = -65.0f; }
        V = Vn;
        __stcs(op + (size_t)t * AX_N, s);
    }
}

extern "C" void kernel_launch(void* const* d_in, const int* in_sizes, int n_in,
                              void* d_out, int out_size) {
    const float* I = (const float*)d_in[0];
    float* S = (float*)d_out;
    const int T = in_sizes[0] / AX_N;   // 2048
    adex_kernel<<<AX_N / BLK, BLK>>>(I, S, T);   // 256 blocks x 128 threads
}